// round 5
// baseline (speedup 1.0000x reference)
#include <cuda_runtime.h>

// AdEx neuron scan, T=2048, N=32768. spikes[t,n] in f32 {0,1}.
// w == 0 identically (A=0, B=0, w0=0) -> dropped.
// Fast path (valid while V <= -20 mV, where 2*exp((V-0.6)/2) < 7e-5 cannot
// affect spiking):  V' = 0.995*V + 0.005*(I - 70), spike = 0.
// Rare path: exact per-batch redo (exp + spike/reset) overwriting the zeros.
//
// R5 vs R4/R3: single fused kernel again (reads+writes concurrently on DRAM;
// the R4 split serialized the two 256MB streams), but fully WARP-AUTONOMOUS:
//  - each warp owns 32 neuron columns; zero-fill of its own 32x32 tile via
//    STG.128 -> no __syncthreads anywhere (R3 had 128 of them).
//  - triple-buffered loads (prefetch distance 2 batches = 8KB in flight per
//    warp, ~56KB/SM) so consumes never wait on DRAM latency (R4 scan was
//    latency-limited at distance 1).
//  - rare path orders its overwrites after the warp's zero-fill with one
//    __syncwarp (cross-lane same-address ordering), never taken on this input.

#define AX_N 32768
#define U 32

__device__ __forceinline__ void load_batch(const float* __restrict__ ip,
                                           int tbase, float (&buf)[U]) {
    #pragma unroll
    for (int k = 0; k < U; ++k)
        buf[k] = __ldcs(ip + (size_t)(tbase + k) * AX_N);
}

// Zero rows [tbase, tbase+U) x this warp's 32 columns (base n0).
// 32x32 floats = 256 float4 = 8 per lane; each STG.128 instr covers 4 rows
// x 128B contiguous segments (fully coalesced sectors).
__device__ __forceinline__ void zero_batch(float* __restrict__ S, int tbase,
                                           int n0, int lane) {
    const float4 z = make_float4(0.f, 0.f, 0.f, 0.f);
    #pragma unroll
    for (int i = 0; i < 8; ++i) {
        const int idx = lane + i * 32;
        const int row = idx >> 3;           // 0..31
        const int col4 = idx & 7;           // 0..7
        __stcs((float4*)(S + (size_t)(tbase + row) * AX_N + n0) + col4, z);
    }
}

// Scan one batch. Fast path: pure FFMA chain, no stores. Rare path: exact
// redo with spike stores (after __syncwarp to order behind the zero-fill).
__device__ __forceinline__ void compute_batch(float* __restrict__ op, int tbase,
                                              const float (&buf)[U], float& V) {
    const float Vs = V;
    float v = V;
    float m = V;
    #pragma unroll
    for (int k = 0; k < U; ++k) {
        v = fmaf(0.995f, v, fmaf(0.005f, buf[k], -0.35f));
        m = fmaxf(m, v);
    }
    if (__any_sync(0xFFFFFFFFu, m > -20.0f)) {
        __syncwarp();                       // zeros(this batch) -> overwrites
        v = Vs;
        #pragma unroll 1
        for (int k = 0; k < U; ++k) {
            const float e = 2.0f * expf((v - 0.6f) * 0.5f);
            float Vn = v + 0.005f * ((-70.0f - v) + e + buf[k]);
            float s = 0.0f;
            if (Vn >= 30.0f) { s = 1.0f; Vn = -65.0f; }
            v = Vn;
            __stcs(op + (size_t)(tbase + k) * AX_N, s);
        }
    }
    V = v;
}

__global__ void __launch_bounds__(32, 1)
adex_kernel(const float* __restrict__ I, float* __restrict__ S, int T) {
    const int lane = threadIdx.x;
    const int n0 = blockIdx.x * 32;          // this warp's column base
    const int n = n0 + lane;
    if (n >= AX_N) return;

    const float* ip = I + n;
    float* op = S + n;

    float V = -70.0f;   // E_L
    float bufA[U], bufB[U], bufC[U];

    const int nb = T / U;          // 64 for T=2048
    int t = 0;

    if (nb > 0) {
        load_batch(ip, 0, bufA);
        if (nb > 1) load_batch(ip, U, bufB);

        for (int b = 0; b < nb; b += 3) {
            if (b + 2 < nb) load_batch(ip, (b + 2) * U, bufC);
            zero_batch(S, b * U, n0, lane);
            compute_batch(op, b * U, bufA, V);
            if (b + 1 >= nb) break;

            if (b + 3 < nb) load_batch(ip, (b + 3) * U, bufA);
            zero_batch(S, (b + 1) * U, n0, lane);
            compute_batch(op, (b + 1) * U, bufB, V);
            if (b + 2 >= nb) break;

            if (b + 4 < nb) load_batch(ip, (b + 4) * U, bufB);
            zero_batch(S, (b + 2) * U, n0, lane);
            compute_batch(op, (b + 2) * U, bufC, V);
        }
        t = nb * U;
    }

    // Scalar tail (T % U != 0): always-exact path with direct stores.
    for (; t < T; ++t) {
        const float iv = __ldcs(ip + (size_t)t * AX_N);
        const float e = 2.0f * expf((V - 0.6f) * 0.5f);
        float Vn = V + 0.005f * ((-70.0f - V) + e + iv);
        float s = 0.0f;
        if (Vn >= 30.0f) { s = 1.0f; Vn = -65.0f; }
        V = Vn;
        __stcs(op + (size_t)t * AX_N, s);
    }
}

extern "C" void kernel_launch(void* const* d_in, const int* in_sizes, int n_in,
                              void* d_out, int out_size) {
    const float* I = (const float*)d_in[0];
    float* S = (float*)d_out;
    const int T = in_sizes[0] / AX_N;   // 2048
    adex_kernel<<<AX_N / 32, 32>>>(I, S, T);   // 1024 one-warp blocks
}

// round 6
// speedup vs baseline: 1.2820x; 1.2820x over previous
#include <cuda_runtime.h>
#include <cstdint>

// AdEx neuron scan, T=2048, N=32768. spikes[t,n] in f32 {0,1}.
// w == 0 identically (A=0, B=0, w0=0) -> dropped.
// Fast path (valid while V <= -20 mV, where 2*exp((V-0.6)/2) < 7e-5 cannot
// affect spiking): V' = 0.995*V + 0.005*(I - 70), spike = 0.
// Rare path: exact per-tile redo (exp + spike/reset), same-thread overwrite.
//
// R6 vs R5: loads go through cp.async (LDGSTS) into SMEM tiles instead of
// register-resident LDG batches. Rationale: per-warp outstanding-LDG is capped
// at M_max~55 -> in-flight bytes/SM were pinned at ~48KB across R2/R3/R5
// (explains the 55% DRAM plateau; warps*width*55 is invariant). LDGSTS has no
// depth cap; SMEM staging gives ~83KB/SM in flight (3 outstanding 8KB tiles x
// 3.46 blocks/SM), ~2x the latency-BW product at NAT clocks.

#define AX_N  32768
#define BLK   64              // threads per block == columns per block
#define RTILE 32              // rows (timesteps) per tile
#define DEPTH 4               // SMEM ring buffers
#define TILE_ELEMS (RTILE * BLK)   // 2048 floats = 8KB

__device__ __forceinline__ void issue_tile(const float* __restrict__ I,
                                           int tile, int slot, int n0, int tid,
                                           float (*buf)[TILE_ELEMS]) {
    const float* gbase = I + (size_t)tile * RTILE * AX_N + n0;
    uint32_t sbase = (uint32_t)__cvta_generic_to_shared(&buf[slot][0]);
    // 8KB tile = 512 16B chunks; 8 per thread. Chunk (r, c): row r, 16B col c.
    #pragma unroll
    for (int j = 0; j < 8; ++j) {
        const int idx = tid + j * BLK;   // 0..511
        const int r = idx >> 4;          // 0..31
        const int c = idx & 15;          // 0..15
        const float* g = gbase + (size_t)r * AX_N + c * 4;
        const uint32_t s = sbase + (uint32_t)(r * BLK + c * 4) * 4u;
        asm volatile("cp.async.cg.shared.global [%0], [%1], 16;\n"
                     :: "r"(s), "l"(g));
    }
    asm volatile("cp.async.commit_group;\n" ::: "memory");
}

__global__ void __launch_bounds__(BLK, 4)
adex_kernel(const float* __restrict__ I, float* __restrict__ S, int T) {
    __shared__ __align__(128) float buf[DEPTH][TILE_ELEMS];

    const int tid = threadIdx.x;
    const int n0 = blockIdx.x * BLK;
    const int n = n0 + tid;

    float* op = S + n;
    float V = -70.0f;   // E_L

    const int ntiles = T / RTILE;

    // Prologue: put DEPTH-1 tiles in flight.
    for (int p = 0; p < DEPTH - 1 && p < ntiles; ++p)
        issue_tile(I, p, p, n0, tid, buf);

    for (int i = 0; i < ntiles; ++i) {
        // Oldest tile (i) complete: allow DEPTH-2 groups still pending.
        asm volatile("cp.async.wait_group %0;\n" :: "n"(DEPTH - 2) : "memory");
        __syncthreads();   // tile i visible to all; compute(i-1) done block-wide

        // Keep DEPTH-1 tiles in flight (writes slot (i-1)%DEPTH, safe: the
        // barrier above ordered it after every thread's compute of tile i-1).
        if (i + DEPTH - 1 < ntiles)
            issue_tile(I, i + DEPTH - 1, (i + DEPTH - 1) % DEPTH, n0, tid, buf);

        const float* tb = buf[i % DEPTH];
        const int t0 = i * RTILE;

        const float Vs = V;
        float v = V;
        float m = V;
        #pragma unroll
        for (int r = 0; r < RTILE; ++r) {
            const float iv = tb[r * BLK + tid];
            v = fmaf(0.995f, v, fmaf(0.005f, iv, -0.35f));
            m = fmaxf(m, v);
            __stcs(op + (size_t)(t0 + r) * AX_N, 0.0f);
        }
        if (__any_sync(0xFFFFFFFFu, m > -20.0f)) {
            // Exact AdEx redo (rare fallback); overwrites this thread's zeros.
            v = Vs;
            #pragma unroll 1
            for (int r = 0; r < RTILE; ++r) {
                const float iv = tb[r * BLK + tid];
                const float e = 2.0f * expf((v - 0.6f) * 0.5f);
                float Vn = v + 0.005f * ((-70.0f - v) + e + iv);
                float s = 0.0f;
                if (Vn >= 30.0f) { s = 1.0f; Vn = -65.0f; }
                v = Vn;
                __stcs(op + (size_t)(t0 + r) * AX_N, s);
            }
        }
        V = v;
    }

    // Scalar tail (T % RTILE != 0): always-exact path, direct global loads.
    for (int t = ntiles * RTILE; t < T; ++t) {
        const float iv = __ldcs(I + (size_t)t * AX_N + n);
        const float e = 2.0f * expf((V - 0.6f) * 0.5f);
        float Vn = V + 0.005f * ((-70.0f - V) + e + iv);
        float s = 0.0f;
        if (Vn >= 30.0f) { s = 1.0f; Vn = -65.0f; }
        V = Vn;
        __stcs(op + (size_t)t * AX_N, s);
    }
}

extern "C" void kernel_launch(void* const* d_in, const int* in_sizes, int n_in,
                              void* d_out, int out_size) {
    const float* I = (const float*)d_in[0];
    float* S = (float*)d_out;
    const int T = in_sizes[0] / AX_N;   // 2048
    adex_kernel<<<AX_N / BLK, BLK>>>(I, S, T);   // 512 blocks x 64 threads
}